// round 3
// baseline (speedup 1.0000x reference)
#include <cuda_runtime.h>
#include <cstdint>
#include <math.h>

#define N_NODES 50000
#define N_EDGES 800000
#define IN_DIM 128
#define EDGE_DIM 16
#define HIDDEN 128
#define N_LAYERS 3
#define N_GRAPHS 256

typedef unsigned long long u64;

// ---------------- scratch (device globals: allocation-free) ----------------
__device__ float g_h[(size_t)N_NODES * HIDDEN];        // node hidden state
__device__ float g_agg[(size_t)N_NODES * HIDDEN];      // scatter-add target
__device__ float g_gi[(size_t)N_NODES * 3 * HIDDEN];   // GRU input gates
__device__ float g_gh[(size_t)N_NODES * 3 * HIDDEN];   // GRU hidden gates
__device__ float g_zsum[N_GRAPHS * HIDDEN];
__device__ unsigned g_zmax[N_GRAPHS * HIDDEN];
__device__ float g_cnt[N_GRAPHS];

// ---------------- packed fp32x2 helpers (FFMA2: 2 MACs/inst) ----------------
__device__ __forceinline__ u64 pack2(float x, float y) {
    u64 r; asm("mov.b64 %0,{%1,%2};" : "=l"(r) : "f"(x), "f"(y)); return r;
}
__device__ __forceinline__ float2 unpack2(u64 v) {
    float2 f; asm("mov.b64 {%0,%1},%2;" : "=f"(f.x), "=f"(f.y) : "l"(v)); return f;
}
__device__ __forceinline__ void fma2(u64& d, u64 a, u64 b) {
    asm("fma.rn.f32x2 %0,%1,%2,%0;" : "+l"(d) : "l"(a), "l"(b));
}

// order-preserving float<->uint for atomicMax
__device__ __forceinline__ unsigned fenc(float f) {
    unsigned u = __float_as_uint(f);
    return (u & 0x80000000u) ? ~u : (u | 0x80000000u);
}
__device__ __forceinline__ float fdec(unsigned u) {
    return __uint_as_float((u & 0x80000000u) ? (u ^ 0x80000000u) : ~u);
}

// ---------------- smem sizes ----------------
#define EDGE_SMEM ((144*128 + 128*128 + 64*144 + 64*128) * 4)   // 208896 B
#define LIN_SMEM  ((128*128 + 32*128) * 4)                       // 81920 B
#define GRU_SMEM  ((128*132 + 32*128) * 4)                       // 83968 B

// ============================================================================
// lin_in: h = relu(x @ W + b), W [128,128] row-major [k][n]
// 256 threads, 32-row tiles, tile-stride loop
// ============================================================================
__global__ __launch_bounds__(256, 2) void lin_in_kernel(
    const float* __restrict__ x, const float* __restrict__ W,
    const float* __restrict__ b)
{
    extern __shared__ float sm[];
    float* sW = sm;              // [128][128]
    float* sA = sW + 128 * 128;  // [32][128]
    const int tid = threadIdx.x;
    for (int i = tid; i < 128 * 128; i += 256) sW[i] = W[i];
    const int warp = tid >> 5, lane = tid & 31;
    const int r0 = warp * 4, c0 = lane * 4;
    const u64 bp0 = pack2(b[c0], b[c0 + 1]), bp1 = pack2(b[c0 + 2], b[c0 + 3]);
    __syncthreads();

    const int ntiles = (N_NODES + 31) / 32;
    for (int t = blockIdx.x; t < ntiles; t += gridDim.x) {
        const int n0 = t * 32;
        {   // load A tile: 8 threads per row
            const int lr = tid >> 3, sub = tid & 7;
            const int n = n0 + lr;
            float4* ap = (float4*)(sA + lr * 128);
            if (n < N_NODES) {
                const float4* xp = (const float4*)(x + (size_t)n * 128);
                #pragma unroll
                for (int i = 0; i < 4; i++) ap[sub * 4 + i] = xp[sub * 4 + i];
            } else {
                float4 z = make_float4(0.f, 0.f, 0.f, 0.f);
                #pragma unroll
                for (int i = 0; i < 4; i++) ap[sub * 4 + i] = z;
            }
        }
        __syncthreads();
        u64 acc[4][2];
        #pragma unroll
        for (int i = 0; i < 4; i++) { acc[i][0] = bp0; acc[i][1] = bp1; }
        const float* A0 = sA + (r0 + 0) * 128;
        const float* A1 = sA + (r0 + 1) * 128;
        const float* A2 = sA + (r0 + 2) * 128;
        const float* A3 = sA + (r0 + 3) * 128;
        #pragma unroll 4
        for (int k = 0; k < 128; k++) {
            const ulonglong2 bv = *(const ulonglong2*)(sW + k * 128 + c0);
            u64 p;
            p = pack2(A0[k], A0[k]); fma2(acc[0][0], p, bv.x); fma2(acc[0][1], p, bv.y);
            p = pack2(A1[k], A1[k]); fma2(acc[1][0], p, bv.x); fma2(acc[1][1], p, bv.y);
            p = pack2(A2[k], A2[k]); fma2(acc[2][0], p, bv.x); fma2(acc[2][1], p, bv.y);
            p = pack2(A3[k], A3[k]); fma2(acc[3][0], p, bv.x); fma2(acc[3][1], p, bv.y);
        }
        #pragma unroll
        for (int i = 0; i < 4; i++) {
            const int n = n0 + r0 + i;
            if (n < N_NODES) {
                float2 x0 = unpack2(acc[i][0]), x1 = unpack2(acc[i][1]);
                *(float4*)(g_h + (size_t)n * 128 + c0) =
                    make_float4(fmaxf(x0.x, 0.f), fmaxf(x0.y, 0.f),
                                fmaxf(x1.x, 0.f), fmaxf(x1.y, 0.f));
            }
        }
        __syncthreads();
    }
}

// ============================================================================
// fused edge message kernel:
//   m = relu([h[src], e_attr] @ W1 + b1) @ W2 + b2 ; atomicAdd into agg[dst]
// 512 threads, 64-edge tiles, W1+W2 resident in SMEM (~138 KB)
// ============================================================================
__global__ __launch_bounds__(512, 1) void edge_msg_kernel(
    const int* __restrict__ src, const int* __restrict__ dst,
    const float* __restrict__ edge_attr,
    const float* __restrict__ W1, const float* __restrict__ b1,
    const float* __restrict__ W2, const float* __restrict__ b2)
{
    extern __shared__ float sm[];
    float* sW1 = sm;               // [144][128]
    float* sW2 = sW1 + 144 * 128;  // [128][128]
    float* sA  = sW2 + 128 * 128;  // [64][144]
    float* sH  = sA + 64 * 144;    // [64][128]
    const int tid = threadIdx.x;
    for (int i = tid; i < 144 * 128; i += 512) sW1[i] = W1[i];
    for (int i = tid; i < 128 * 128; i += 512) sW2[i] = W2[i];
    const int warp = tid >> 5, lane = tid & 31;
    const int r0 = warp * 4, c0 = lane * 4;
    const u64 b1p0 = pack2(b1[c0], b1[c0 + 1]), b1p1 = pack2(b1[c0 + 2], b1[c0 + 3]);
    const u64 b2p0 = pack2(b2[c0], b2[c0 + 1]), b2p1 = pack2(b2[c0 + 2], b2[c0 + 3]);
    __syncthreads();

    const int ntiles = N_EDGES / 64;   // 12500 exact
    for (int t = blockIdx.x; t < ntiles; t += gridDim.x) {
        const int e0 = t * 64;
        {   // gather inputs: 8 threads per edge
            const int le = tid >> 3, sub = tid & 7;
            const int e = e0 + le;
            const int s = src[e];
            const float4* hp = (const float4*)(g_h + (size_t)s * 128);
            float4* ap = (float4*)(sA + le * 144);
            #pragma unroll
            for (int i = 0; i < 4; i++) ap[sub * 4 + i] = hp[sub * 4 + i];
            const float2 ea = *(const float2*)(edge_attr + (size_t)e * 16 + sub * 2);
            sA[le * 144 + 128 + sub * 2]     = ea.x;
            sA[le * 144 + 128 + sub * 2 + 1] = ea.y;
        }
        __syncthreads();

        // GEMM1: hid = relu(A[64,144] @ W1 + b1)
        u64 acc[4][2];
        #pragma unroll
        for (int i = 0; i < 4; i++) { acc[i][0] = b1p0; acc[i][1] = b1p1; }
        {
            const float* A0 = sA + (r0 + 0) * 144;
            const float* A1 = sA + (r0 + 1) * 144;
            const float* A2 = sA + (r0 + 2) * 144;
            const float* A3 = sA + (r0 + 3) * 144;
            #pragma unroll 4
            for (int k = 0; k < 144; k++) {
                const ulonglong2 bv = *(const ulonglong2*)(sW1 + k * 128 + c0);
                u64 p;
                p = pack2(A0[k], A0[k]); fma2(acc[0][0], p, bv.x); fma2(acc[0][1], p, bv.y);
                p = pack2(A1[k], A1[k]); fma2(acc[1][0], p, bv.x); fma2(acc[1][1], p, bv.y);
                p = pack2(A2[k], A2[k]); fma2(acc[2][0], p, bv.x); fma2(acc[2][1], p, bv.y);
                p = pack2(A3[k], A3[k]); fma2(acc[3][0], p, bv.x); fma2(acc[3][1], p, bv.y);
            }
        }
        #pragma unroll
        for (int i = 0; i < 4; i++) {
            float2 x0 = unpack2(acc[i][0]), x1 = unpack2(acc[i][1]);
            *(float4*)(sH + (r0 + i) * 128 + c0) =
                make_float4(fmaxf(x0.x, 0.f), fmaxf(x0.y, 0.f),
                            fmaxf(x1.x, 0.f), fmaxf(x1.y, 0.f));
        }
        __syncthreads();

        // GEMM2: m = hid[64,128] @ W2 + b2
        #pragma unroll
        for (int i = 0; i < 4; i++) { acc[i][0] = b2p0; acc[i][1] = b2p1; }
        {
            const float* H0 = sH + (r0 + 0) * 128;
            const float* H1 = sH + (r0 + 1) * 128;
            const float* H2 = sH + (r0 + 2) * 128;
            const float* H3 = sH + (r0 + 3) * 128;
            #pragma unroll 4
            for (int k = 0; k < 128; k++) {
                const ulonglong2 bv = *(const ulonglong2*)(sW2 + k * 128 + c0);
                u64 p;
                p = pack2(H0[k], H0[k]); fma2(acc[0][0], p, bv.x); fma2(acc[0][1], p, bv.y);
                p = pack2(H1[k], H1[k]); fma2(acc[1][0], p, bv.x); fma2(acc[1][1], p, bv.y);
                p = pack2(H2[k], H2[k]); fma2(acc[2][0], p, bv.x); fma2(acc[2][1], p, bv.y);
                p = pack2(H3[k], H3[k]); fma2(acc[3][0], p, bv.x); fma2(acc[3][1], p, bv.y);
            }
        }
        // scatter-add to agg[dst]
        #pragma unroll
        for (int i = 0; i < 4; i++) {
            const int e = e0 + r0 + i;
            const int d = dst[e];
            float* o = g_agg + (size_t)d * 128 + c0;
            float2 x0 = unpack2(acc[i][0]), x1 = unpack2(acc[i][1]);
            atomicAdd(o + 0, x0.x);
            atomicAdd(o + 1, x0.y);
            atomicAdd(o + 2, x1.x);
            atomicAdd(o + 3, x1.y);
        }
        __syncthreads();
    }
}

// ============================================================================
// GRU gemms: gi = agg @ wih^T + bih ; gh = h @ whh^T + bhh
// grid.y in [0,6): which = y/3 (0:gi, 1:gh), gate = y%3. W chunk transposed to
// smem [k][j] with pad-132 stride.
// ============================================================================
__global__ __launch_bounds__(256, 2) void gru_gemm_kernel(
    const float* __restrict__ wih, const float* __restrict__ whh,
    const float* __restrict__ bih, const float* __restrict__ bhh)
{
    extern __shared__ float sm[];
    float* sW = sm;              // [128][132] transposed chunk
    float* sA = sW + 128 * 132;  // [32][128]
    const int which = blockIdx.y / 3;
    const int gate  = blockIdx.y % 3;
    const float* W    = (which ? whh : wih) + (size_t)gate * 128 * 128;
    const float* bias = (which ? bhh : bih) + gate * 128;
    const float* A    = which ? g_h : g_agg;
    float* out        = which ? g_gh : g_gi;

    const int tid = threadIdx.x;
    for (int i = tid; i < 128 * 128; i += 256) {
        int j = i >> 7, k = i & 127;
        sW[k * 132 + j] = W[i];     // W[j*128+k] -> sW[k][j]
    }
    const int warp = tid >> 5, lane = tid & 31;
    const int r0 = warp * 4, c0 = lane * 4;
    const u64 bp0 = pack2(bias[c0], bias[c0 + 1]), bp1 = pack2(bias[c0 + 2], bias[c0 + 3]);
    __syncthreads();

    const int ntiles = (N_NODES + 31) / 32;
    for (int t = blockIdx.x; t < ntiles; t += gridDim.x) {
        const int n0 = t * 32;
        {
            const int lr = tid >> 3, sub = tid & 7;
            const int n = n0 + lr;
            float4* ap = (float4*)(sA + lr * 128);
            if (n < N_NODES) {
                const float4* xp = (const float4*)(A + (size_t)n * 128);
                #pragma unroll
                for (int i = 0; i < 4; i++) ap[sub * 4 + i] = xp[sub * 4 + i];
            } else {
                float4 z = make_float4(0.f, 0.f, 0.f, 0.f);
                #pragma unroll
                for (int i = 0; i < 4; i++) ap[sub * 4 + i] = z;
            }
        }
        __syncthreads();
        u64 acc[4][2];
        #pragma unroll
        for (int i = 0; i < 4; i++) { acc[i][0] = bp0; acc[i][1] = bp1; }
        const float* A0 = sA + (r0 + 0) * 128;
        const float* A1 = sA + (r0 + 1) * 128;
        const float* A2 = sA + (r0 + 2) * 128;
        const float* A3 = sA + (r0 + 3) * 128;
        #pragma unroll 4
        for (int k = 0; k < 128; k++) {
            const ulonglong2 bv = *(const ulonglong2*)(sW + k * 132 + c0);
            u64 p;
            p = pack2(A0[k], A0[k]); fma2(acc[0][0], p, bv.x); fma2(acc[0][1], p, bv.y);
            p = pack2(A1[k], A1[k]); fma2(acc[1][0], p, bv.x); fma2(acc[1][1], p, bv.y);
            p = pack2(A2[k], A2[k]); fma2(acc[2][0], p, bv.x); fma2(acc[2][1], p, bv.y);
            p = pack2(A3[k], A3[k]); fma2(acc[3][0], p, bv.x); fma2(acc[3][1], p, bv.y);
        }
        #pragma unroll
        for (int i = 0; i < 4; i++) {
            const int n = n0 + r0 + i;
            if (n < N_NODES) {
                float2 x0 = unpack2(acc[i][0]), x1 = unpack2(acc[i][1]);
                *(float4*)(out + (size_t)n * 384 + gate * 128 + c0) =
                    make_float4(x0.x, x0.y, x1.x, x1.y);
            }
        }
        __syncthreads();
    }
}

// ============================================================================
// fused GRU gates + BatchNorm + residual
// ============================================================================
__global__ void gru_gate_kernel(
    const float* __restrict__ gamma, const float* __restrict__ beta,
    const float* __restrict__ mean, const float* __restrict__ var)
{
    const int idx = blockIdx.x * blockDim.x + threadIdx.x;
    if (idx >= N_NODES * HIDDEN) return;
    const int c = idx & 127;
    const size_t n = (size_t)(idx >> 7);
    const float* gi = g_gi + n * 384;
    const float* gh = g_gh + n * 384;
    const float hv = g_h[idx];
    const float r = 1.f / (1.f + expf(-(gi[c] + gh[c])));
    const float z = 1.f / (1.f + expf(-(gi[128 + c] + gh[128 + c])));
    const float nn = tanhf(gi[256 + c] + r * gh[256 + c]);
    const float hnew = (1.f - z) * nn + z * hv;
    const float bn = (hnew - mean[c]) * rsqrtf(var[c] + 1e-5f) * gamma[c] + beta[c];
    g_h[idx] = hv + bn;
}

// ---------------- aux kernels ----------------
__global__ void zero_agg_kernel() {
    const int idx = blockIdx.x * blockDim.x + threadIdx.x;
    if (idx < N_NODES * HIDDEN / 4)
        ((float4*)g_agg)[idx] = make_float4(0.f, 0.f, 0.f, 0.f);
}

__global__ void init_readout_kernel() {
    const int idx = blockIdx.x * blockDim.x + threadIdx.x;
    if (idx < N_GRAPHS * HIDDEN) { g_zsum[idx] = 0.f; g_zmax[idx] = 0x00800000u; }
    if (idx < N_GRAPHS) g_cnt[idx] = 0.f;
}

__global__ void seg_reduce_kernel(const int* __restrict__ batch) {
    const int gid = blockIdx.x * blockDim.x + threadIdx.x;   // N_NODES*32
    if (gid >= N_NODES * 32) return;
    const int n = gid >> 5, q = gid & 31;
    const int g = batch[n];
    const float4 hv = *(const float4*)(g_h + (size_t)n * 128 + q * 4);
    float* zs = g_zsum + g * 128 + q * 4;
    atomicAdd(zs + 0, hv.x); atomicAdd(zs + 1, hv.y);
    atomicAdd(zs + 2, hv.z); atomicAdd(zs + 3, hv.w);
    unsigned* zm = g_zmax + g * 128 + q * 4;
    atomicMax(zm + 0, fenc(hv.x)); atomicMax(zm + 1, fenc(hv.y));
    atomicMax(zm + 2, fenc(hv.z)); atomicMax(zm + 3, fenc(hv.w));
    if (q == 0) atomicAdd(g_cnt + g, 1.f);
}

__global__ void readout_kernel(const float* __restrict__ ro_w,
                               const float* __restrict__ ro_b,
                               float* __restrict__ out)
{
    __shared__ float sbuf[256];
    const int g = blockIdx.x, j = threadIdx.x;   // 128 threads
    const float c = g_cnt[g];
    const float inv = 1.f / fmaxf(c, 1.f);
    sbuf[j]       = g_zsum[g * 128 + j] * inv;
    sbuf[128 + j] = (c > 0.f) ? fdec(g_zmax[g * 128 + j]) : 0.f;
    __syncthreads();
    float acc = ro_b[j];
    #pragma unroll 8
    for (int k = 0; k < 256; k++) acc = fmaf(sbuf[k], ro_w[k * 128 + j], acc);
    out[g * 128 + j] = fmaxf(acc, 0.f);
}

// ============================================================================
extern "C" void kernel_launch(void* const* d_in, const int* in_sizes, int n_in,
                              void* d_out, int out_size)
{
    // setup_inputs order; n_graphs (scalar) may or may not appear as input 4
    const int shift = (in_sizes[4] == 1) ? 1 : 0;
    const float* x         = (const float*)d_in[0];
    const int*   edge_idx  = (const int*)  d_in[1];
    const float* edge_attr = (const float*)d_in[2];
    const int*   batch     = (const int*)  d_in[3];
    const float* lin_in_w  = (const float*)d_in[4 + shift];
    const float* lin_in_b  = (const float*)d_in[5 + shift];
    const float* msg_w1    = (const float*)d_in[6 + shift];
    const float* msg_b1    = (const float*)d_in[7 + shift];
    const float* msg_w2    = (const float*)d_in[8 + shift];
    const float* msg_b2    = (const float*)d_in[9 + shift];
    const float* bn_gamma  = (const float*)d_in[10 + shift];
    const float* bn_beta   = (const float*)d_in[11 + shift];
    const float* bn_mean   = (const float*)d_in[12 + shift];
    const float* bn_var    = (const float*)d_in[13 + shift];
    const float* gru_wih   = (const float*)d_in[14 + shift];
    const float* gru_whh   = (const float*)d_in[15 + shift];
    const float* gru_bih   = (const float*)d_in[16 + shift];
    const float* gru_bhh   = (const float*)d_in[17 + shift];
    const float* ro_w      = (const float*)d_in[18 + shift];
    const float* ro_b      = (const float*)d_in[19 + shift];
    float* out = (float*)d_out;

    static bool inited = false;
    if (!inited) {
        cudaFuncSetAttribute(edge_msg_kernel, cudaFuncAttributeMaxDynamicSharedMemorySize, EDGE_SMEM);
        cudaFuncSetAttribute(lin_in_kernel,   cudaFuncAttributeMaxDynamicSharedMemorySize, LIN_SMEM);
        cudaFuncSetAttribute(gru_gemm_kernel, cudaFuncAttributeMaxDynamicSharedMemorySize, GRU_SMEM);
        inited = true;
    }

    const int* src = edge_idx;
    const int* dst = edge_idx + N_EDGES;

    lin_in_kernel<<<296, 256, LIN_SMEM>>>(x, lin_in_w, lin_in_b);

    for (int l = 0; l < N_LAYERS; l++) {
        zero_agg_kernel<<<(N_NODES * HIDDEN / 4 + 255) / 256, 256>>>();
        edge_msg_kernel<<<148, 512, EDGE_SMEM>>>(
            src, dst, edge_attr,
            msg_w1 + (size_t)l * 144 * 128, msg_b1 + l * 128,
            msg_w2 + (size_t)l * 128 * 128, msg_b2 + l * 128);
        gru_gemm_kernel<<<dim3(296, 6), 256, GRU_SMEM>>>(
            gru_wih + (size_t)l * 384 * 128, gru_whh + (size_t)l * 384 * 128,
            gru_bih + l * 384, gru_bhh + l * 384);
        gru_gate_kernel<<<(N_NODES * HIDDEN + 255) / 256, 256>>>(
            bn_gamma + l * 128, bn_beta + l * 128, bn_mean + l * 128, bn_var + l * 128);
    }

    init_readout_kernel<<<(N_GRAPHS * HIDDEN + 255) / 256, 256>>>();
    seg_reduce_kernel<<<(N_NODES * 32 + 255) / 256, 256>>>(batch);
    readout_kernel<<<N_GRAPHS, 128>>>(ro_w, ro_b, out);
}